// round 15
// baseline (speedup 1.0000x reference)
#include <cuda_runtime.h>
#include <cuda_fp16.h>
#include <cstdint>
#include <math.h>

// Problem constants
#define BATCH   16
#define CC      192
#define NHEAD   6
#define NTOK    64
#define NWIN    64
#define MROWS   65536
#define QKVDIM  576
#define MLPDIM  768
#define SCALE_Q 0.17677669529663687f

// Weight half-buffer offsets (elements)
#define WOFF_QKV  0
#define WOFF_PROJ 221184
#define WOFF_FC1  294912
#define WOFF_FC2  589824
#define WTOTAL    884736

// Scratch (device globals)
__device__ __half g_ah[(size_t)MROWS * 192];   // activations hi (GEMM A inputs)
__device__ __half g_bh[(size_t)MROWS * 768];   // qkv / gelu hi
__device__ __half g_bl[(size_t)MROWS * 768];   // qkv lo (attention only)
__device__ __half g_wh[WTOTAL];                // weights hi only

// ---------------------------------------------------------------------------
// PTX helpers
// ---------------------------------------------------------------------------
__device__ __forceinline__ uint32_t smem_u32(const void* p) {
    uint32_t a;
    asm("{ .reg .u64 t; cvta.to.shared.u64 t, %1; cvt.u32.u64 %0, t; }"
        : "=r"(a) : "l"(p));
    return a;
}

#define CP16(dst, src) \
    asm volatile("cp.async.cg.shared.global [%0], [%1], 16;" :: "r"(dst), "l"(src))

#define LDSM4(r0, r1, r2, r3, addr) \
    asm volatile("ldmatrix.sync.aligned.m8n8.x4.shared.b16 {%0,%1,%2,%3}, [%4];" \
        : "=r"(r0), "=r"(r1), "=r"(r2), "=r"(r3) : "r"(addr))

#define LDSM4T(r0, r1, r2, r3, addr) \
    asm volatile("ldmatrix.sync.aligned.m8n8.x4.trans.shared.b16 {%0,%1,%2,%3}, [%4];" \
        : "=r"(r0), "=r"(r1), "=r"(r2), "=r"(r3) : "r"(addr))

#define MMA16816(d, a, b0, b1) \
    asm volatile("mma.sync.aligned.m16n8k16.row.col.f32.f16.f16.f32 " \
        "{%0,%1,%2,%3},{%4,%5,%6,%7},{%8,%9},{%0,%1,%2,%3};" \
        : "+f"((d)[0]), "+f"((d)[1]), "+f"((d)[2]), "+f"((d)[3]) \
        : "r"((a)[0]), "r"((a)[1]), "r"((a)[2]), "r"((a)[3]), "r"(b0), "r"(b1))

__device__ __forceinline__ uint32_t pack_hi(float x, float y) {
    __half2 h = __halves2half2(__float2half(x), __float2half(y));
    return *(uint32_t*)&h;
}
__device__ __forceinline__ uint32_t pack_lo(float x, float y) {
    __half hx = __float2half(x), hy = __float2half(y);
    __half2 h = __halves2half2(__float2half(x - __half2float(hx)),
                               __float2half(y - __half2float(hy)));
    return *(uint32_t*)&h;
}

// ---------------------------------------------------------------------------
// Weight conversion: two fp32 arrays -> hi fp16 only
// ---------------------------------------------------------------------------
__global__ __launch_bounds__(256) void cvt2_kernel(
    const float* __restrict__ s1, __half* __restrict__ h1, int n1,
    const float* __restrict__ s2, __half* __restrict__ h2, int n2)
{
    int i = blockIdx.x * 256 + threadIdx.x;
    if (i < n1) h1[i] = __float2half(s1[i]);
    else if (i < n1 + n2) h2[i - n1] = __float2half(s2[i - n1]);
}

// ---------------------------------------------------------------------------
// LayerNorm (+ optional shift + window partition) -> fp16 hi only
// ---------------------------------------------------------------------------
__global__ __launch_bounds__(256) void ln_kernel(
    const float* __restrict__ x, const float* __restrict__ gam,
    const float* __restrict__ bet, __half* __restrict__ oh,
    int shift, int windowed)
{
    int warp = threadIdx.x >> 5, lane = threadIdx.x & 31;
    int r = blockIdx.x * 8 + warp;
    int src;
    if (windowed) {
        int bw = r >> 6, tok = r & 63;
        int b_img = bw >> 6, wr = (bw >> 3) & 7, wc = bw & 7;
        int ti = tok >> 3, tj = tok & 7;
        int h = (wr * 8 + ti + shift) & 63;
        int w = (wc * 8 + tj + shift) & 63;
        src = b_img * 4096 + h * 64 + w;
    } else src = r;
    const float* xp = x + (size_t)src * CC;
    float v[6];
    float s = 0.f;
#pragma unroll
    for (int j = 0; j < 6; j++) { v[j] = xp[lane + 32 * j]; s += v[j]; }
#pragma unroll
    for (int o = 16; o; o >>= 1) s += __shfl_xor_sync(0xffffffffu, s, o);
    float mu = s * (1.f / 192.f);
    float q = 0.f;
#pragma unroll
    for (int j = 0; j < 6; j++) { float d = v[j] - mu; q += d * d; }
#pragma unroll
    for (int o = 16; o; o >>= 1) q += __shfl_xor_sync(0xffffffffu, q, o);
    float rstd = rsqrtf(q * (1.f / 192.f) + 1e-5f);
    size_t base = (size_t)r * CC;
#pragma unroll
    for (int j = 0; j < 6; j++) {
        int c = lane + 32 * j;
        float y = (v[j] - mu) * rstd * gam[c] + bet[c];
        oh[base + c] = __float2half(y);
    }
}

// ---------------------------------------------------------------------------
// Pure fp16 tensor GEMM: C = A[M,K] @ W[N,K]^T + bias (1 MMA per k16).
// BM=128, BN=64, BK=64, 256 threads (8 warps, 4x2), warp tile 32x32.
// 3-stage cp.async ring, ONE __syncthreads per k-iteration, 3 CTAs/SM.
// ---------------------------------------------------------------------------
#define MODE_QKV     0   // writes hi AND lo (attention consumes both)
#define MODE_GELU_H  1   // writes hi only
#define MODE_RESADD  2
#define MODE_PROJ    3

// stage: Ah 16K @0, Bh 8K @16384
#define STAGE_BYTES 24576
#define GEMM_SMEM   (3 * STAGE_BYTES)   // 73728

__device__ __forceinline__ int proj_dest(int r, int shift) {
    int bw = r >> 6, tok = r & 63;
    int b_img = bw >> 6, wr = (bw >> 3) & 7, wc = bw & 7;
    int ti = tok >> 3, tj = tok & 7;
    int h = (wr * 8 + ti + shift) & 63;
    int w = (wc * 8 + tj + shift) & 63;
    return b_img * 4096 + h * 64 + w;
}

template<int MODE>
__global__ __launch_bounds__(256, 3) void gemm_mma(
    const __half* __restrict__ Ah,
    const __half* __restrict__ Bh,
    const float* __restrict__ bias, float* __restrict__ Cp,
    __half* __restrict__ Oh, __half* __restrict__ Ol,
    const float* __restrict__ Rsrc,
    int N, int K, int shift)
{
    extern __shared__ char smem[];
    const uint32_t smbase = smem_u32(smem);
    const int tid  = threadIdx.x;
    const int lane = tid & 31, warp = tid >> 5;
    const int wm = warp >> 1, wn = warp & 1;
    const int m0 = blockIdx.y * 128, n0 = blockIdx.x * 64;
    const int lc = tid & 7;
    const int lr = tid >> 3;

    const __half* pAh = Ah + (size_t)m0 * K + lc * 8;
    const __half* pBh = Bh + (size_t)n0 * K + lc * 8;

    const int niter = K >> 6;

    auto stage_base = [&](int s) -> uint32_t {
        int b = s;  // s % 3 without divide: handled by caller pattern
        b = (b >= 3) ? b - 3 : b;
        b = (b >= 3) ? b - 3 : b;
        b = (b >= 3) ? b - 3 : b;
        b = (b >= 3) ? b - 3 : b;
        return smbase + (uint32_t)b * STAGE_BYTES;
    };

    auto issue = [&](int s) {
        uint32_t sb = stage_base(s);
        int k0 = s << 6;
#pragma unroll
        for (int i = 0; i < 4; i++) {
            int r = lr + 32 * i;
            uint32_t d = sb + r * 128 + ((uint32_t)(lc ^ (r & 7)) << 4);
            CP16(d, pAh + (size_t)r * K + k0);
        }
#pragma unroll
        for (int i = 0; i < 2; i++) {
            int r = lr + 32 * i;
            uint32_t d = sb + 16384 + r * 128 + ((uint32_t)(lc ^ (r & 7)) << 4);
            CP16(d, pBh + (size_t)r * K + k0);
        }
        asm volatile("cp.async.commit_group;");
    };

    float acc[2][4][4];
#pragma unroll
    for (int i = 0; i < 2; i++)
#pragma unroll
        for (int j = 0; j < 4; j++)
#pragma unroll
            for (int e = 0; e < 4; e++) acc[i][j][e] = 0.f;

    issue(0);
    if (niter > 1) issue(1);

    for (int s = 0; s < niter; s++) {
        if (s + 1 < niter) asm volatile("cp.async.wait_group 1;");
        else               asm volatile("cp.async.wait_group 0;");
        __syncthreads();
        if (s + 2 < niter) issue(s + 2);

        uint32_t sb = stage_base(s);
#pragma unroll
        for (int kk = 0; kk < 4; kk++) {
            uint32_t aH[2][4], bH[2][4];
#pragma unroll
            for (int i = 0; i < 2; i++) {
                int r  = wm * 32 + i * 16 + (lane & 15);
                int ch = kk * 2 + (lane >> 4);
                uint32_t ad = sb + r * 128 + ((uint32_t)(ch ^ (r & 7)) << 4);
                LDSM4(aH[i][0], aH[i][1], aH[i][2], aH[i][3], ad);
            }
#pragma unroll
            for (int i = 0; i < 2; i++) {
                int grp = lane >> 3;
                int r  = wn * 32 + i * 16 + ((grp >> 1) << 3) + (lane & 7);
                int ch = kk * 2 + (grp & 1);
                uint32_t bd = sb + 16384 + r * 128 + ((uint32_t)(ch ^ (r & 7)) << 4);
                LDSM4(bH[i][0], bH[i][1], bH[i][2], bH[i][3], bd);
            }
#pragma unroll
            for (int i = 0; i < 2; i++)
#pragma unroll
                for (int jj = 0; jj < 4; jj++) {
                    int bi = jj >> 1, bo = (jj & 1) * 2;
                    MMA16816(acc[i][jj], aH[i], bH[bi][bo], bH[bi][bo + 1]);
                }
        }
    }

    // epilogue
#pragma unroll
    for (int i = 0; i < 2; i++) {
        int rb = m0 + wm * 32 + i * 16 + (lane >> 2);
#pragma unroll
        for (int hf = 0; hf < 2; hf++) {
            int r = rb + hf * 8;
            int dest = (MODE == MODE_PROJ) ? proj_dest(r, shift) : r;
#pragma unroll
            for (int jj = 0; jj < 4; jj++) {
                int c = n0 + wn * 32 + jj * 8 + (lane & 3) * 2;
                float v0 = acc[i][jj][hf * 2 + 0] + bias[c];
                float v1 = acc[i][jj][hf * 2 + 1] + bias[c + 1];
                if (MODE == MODE_QKV) {
                    if (c < 192) { v0 *= SCALE_Q; v1 *= SCALE_Q; }
                    __half h0 = __float2half(v0), h1 = __float2half(v1);
                    *(__half2*)(Oh + (size_t)r * N + c) = __halves2half2(h0, h1);
                    *(__half2*)(Ol + (size_t)r * N + c) = __halves2half2(
                        __float2half(v0 - __half2float(h0)),
                        __float2half(v1 - __half2float(h1)));
                } else if (MODE == MODE_GELU_H) {
                    float g0 = 0.5f * v0 * (1.f + erff(v0 * 0.70710678118654752f));
                    float g1 = 0.5f * v1 * (1.f + erff(v1 * 0.70710678118654752f));
                    *(__half2*)(Oh + (size_t)r * N + c) =
                        __halves2half2(__float2half(g0), __float2half(g1));
                } else if (MODE == MODE_RESADD) {
                    float2* p = (float2*)(Cp + (size_t)r * N + c);
                    float2 o = *p; o.x += v0; o.y += v1; *p = o;
                } else { // MODE_PROJ
                    float2 rv = *(const float2*)(Rsrc + (size_t)dest * CC + c);
                    float2 o; o.x = rv.x + v0; o.y = rv.y + v1;
                    *(float2*)(Cp + (size_t)dest * CC + c) = o;
                }
            }
        }
    }
}

// ---------------------------------------------------------------------------
// Tensor-core windowed attention: one CTA = 2 heads (128 threads).
// Full 3-term hi/lo precision for q,k,v; output hi only. (unchanged)
// ---------------------------------------------------------------------------
struct __align__(16) AttnSmem2 {
    __half qh[2][2048], ql[2][2048];
    __half kh[2][2048], kl[2][2048];
    __half vh[2][2048], vl[2][2048];
    float  tbl[2][225];
    unsigned char rel[4096];
    int    rid[64];
};
#define ATTN_SMEM ((int)sizeof(AttnSmem2))

__global__ __launch_bounds__(128) void attn_mma(
    const __half* __restrict__ Qh, const __half* __restrict__ Ql,
    const float* __restrict__ tblg,
    __half* __restrict__ oh, int shift)
{
    extern __shared__ char smraw[];
    AttnSmem2& sm = *reinterpret_cast<AttnSmem2*>(smraw);
    int bw = blockIdx.y;
    int tid = threadIdx.x;
    int sub = tid >> 6, t64 = tid & 63;
    int lane = tid & 31, wq = (t64 >> 5);
    int head = blockIdx.x * 2 + sub;

    __half* bufs[6] = {sm.qh[sub], sm.ql[sub], sm.kh[sub], sm.kl[sub],
                       sm.vh[sub], sm.vl[sub]};
#pragma unroll
    for (int it = 0; it < 24; it++) {
        int idx = t64 + it * 64;
        int buf = idx >> 8, rem = idx & 255, r = rem >> 2, ch = rem & 3;
        int sec = buf >> 1;
        const __half* src = (buf & 1) ? Ql : Qh;
        const __half* p = src + (size_t)(bw * 64 + r) * QKVDIM + sec * 192 + head * 32 + ch * 8;
        uint4 val = *(const uint4*)p;
        *(uint4*)((char*)bufs[buf] + r * 64 + ((ch ^ (r & 3)) << 4)) = val;
    }
    for (int idx = tid; idx < 4096; idx += 128) {
        int n = idx >> 6, m = idx & 63;
        sm.rel[idx] = (unsigned char)(((n >> 3) - (m >> 3) + 7) * 15 + ((n & 7) - (m & 7) + 7));
    }
    for (int idx = t64; idx < 225; idx += 64) sm.tbl[sub][idx] = tblg[idx * NHEAD + head];
    if (tid < 64) {
        int wr = (bw >> 3) & 7, wc = bw & 7;
        int ti = tid >> 3, tj = tid & 7;
        int h = wr * 8 + ti, w = wc * 8 + tj;
        int rh = (h < 56) ? 0 : ((h < 60) ? 1 : 2);
        int rw = (w < 56) ? 0 : ((w < 60) ? 1 : 2);
        sm.rid[tid] = rh * 3 + rw;
    }
    __syncthreads();

    uint32_t qhb = smem_u32(sm.qh[sub]), qlb = smem_u32(sm.ql[sub]);
    uint32_t khb = smem_u32(sm.kh[sub]), klb = smem_u32(sm.kl[sub]);
    uint32_t vhb = smem_u32(sm.vh[sub]), vlb = smem_u32(sm.vl[sub]);

    float sc[2][8][4];
#pragma unroll
    for (int i = 0; i < 2; i++)
#pragma unroll
        for (int j = 0; j < 8; j++)
#pragma unroll
            for (int e = 0; e < 4; e++) sc[i][j][e] = 0.f;

#pragma unroll
    for (int kk = 0; kk < 2; kk++) {
        uint32_t aH[2][4], aL[2][4], bH[4][4], bL[4][4];
#pragma unroll
        for (int i = 0; i < 2; i++) {
            int r  = wq * 32 + i * 16 + (lane & 15);
            int ch = kk * 2 + (lane >> 4);
            uint32_t off = (uint32_t)(r * 64 + ((ch ^ (r & 3)) << 4));
            LDSM4(aH[i][0], aH[i][1], aH[i][2], aH[i][3], qhb + off);
            LDSM4(aL[i][0], aL[i][1], aL[i][2], aL[i][3], qlb + off);
        }
#pragma unroll
        for (int i = 0; i < 4; i++) {
            int grp = lane >> 3;
            int r  = i * 16 + ((grp >> 1) << 3) + (lane & 7);
            int ch = kk * 2 + (grp & 1);
            uint32_t off = (uint32_t)(r * 64 + ((ch ^ (r & 3)) << 4));
            LDSM4(bH[i][0], bH[i][1], bH[i][2], bH[i][3], khb + off);
            LDSM4(bL[i][0], bL[i][1], bL[i][2], bL[i][3], klb + off);
        }
#pragma unroll
        for (int i = 0; i < 2; i++)
#pragma unroll
            for (int j = 0; j < 8; j++) {
                int bi = j >> 1, bo = (j & 1) * 2;
                MMA16816(sc[i][j], aH[i], bH[bi][bo], bH[bi][bo + 1]);
            }
#pragma unroll
        for (int i = 0; i < 2; i++)
#pragma unroll
            for (int j = 0; j < 8; j++) {
                int bi = j >> 1, bo = (j & 1) * 2;
                MMA16816(sc[i][j], aH[i], bL[bi][bo], bL[bi][bo + 1]);
            }
#pragma unroll
        for (int i = 0; i < 2; i++)
#pragma unroll
            for (int j = 0; j < 8; j++) {
                int bi = j >> 1, bo = (j & 1) * 2;
                MMA16816(sc[i][j], aL[i], bH[bi][bo], bH[bi][bo + 1]);
            }
    }

    int gr = lane >> 2, lam = lane & 3;
    float invs[2][2];
#pragma unroll
    for (int i = 0; i < 2; i++) {
        int rA = wq * 32 + i * 16 + gr, rB = rA + 8;
        int ridA = sm.rid[rA], ridB = sm.rid[rB];
        float mxA = -1e30f, mxB = -1e30f;
#pragma unroll
        for (int j = 0; j < 8; j++) {
            int c0 = 8 * j + 2 * lam;
            float b00 = sm.tbl[sub][sm.rel[rA * 64 + c0]];
            float b01 = sm.tbl[sub][sm.rel[rA * 64 + c0 + 1]];
            float b10 = sm.tbl[sub][sm.rel[rB * 64 + c0]];
            float b11 = sm.tbl[sub][sm.rel[rB * 64 + c0 + 1]];
            if (shift) {
                int rc0 = sm.rid[c0], rc1 = sm.rid[c0 + 1];
                if (rc0 != ridA) b00 -= 100.f;
                if (rc1 != ridA) b01 -= 100.f;
                if (rc0 != ridB) b10 -= 100.f;
                if (rc1 != ridB) b11 -= 100.f;
            }
            sc[i][j][0] += b00; sc[i][j][1] += b01;
            sc[i][j][2] += b10; sc[i][j][3] += b11;
            mxA = fmaxf(mxA, fmaxf(sc[i][j][0], sc[i][j][1]));
            mxB = fmaxf(mxB, fmaxf(sc[i][j][2], sc[i][j][3]));
        }
        mxA = fmaxf(mxA, __shfl_xor_sync(0xffffffffu, mxA, 1));
        mxA = fmaxf(mxA, __shfl_xor_sync(0xffffffffu, mxA, 2));
        mxB = fmaxf(mxB, __shfl_xor_sync(0xffffffffu, mxB, 1));
        mxB = fmaxf(mxB, __shfl_xor_sync(0xffffffffu, mxB, 2));
        float sA = 0.f, sB = 0.f;
#pragma unroll
        for (int j = 0; j < 8; j++) {
            sc[i][j][0] = __expf(sc[i][j][0] - mxA); sA += sc[i][j][0];
            sc[i][j][1] = __expf(sc[i][j][1] - mxA); sA += sc[i][j][1];
            sc[i][j][2] = __expf(sc[i][j][2] - mxB); sB += sc[i][j][2];
            sc[i][j][3] = __expf(sc[i][j][3] - mxB); sB += sc[i][j][3];
        }
        sA += __shfl_xor_sync(0xffffffffu, sA, 1);
        sA += __shfl_xor_sync(0xffffffffu, sA, 2);
        sB += __shfl_xor_sync(0xffffffffu, sB, 1);
        sB += __shfl_xor_sync(0xffffffffu, sB, 2);
        invs[i][0] = 1.f / sA;
        invs[i][1] = 1.f / sB;
    }

    float out[2][4][4];
#pragma unroll
    for (int i = 0; i < 2; i++)
#pragma unroll
        for (int j = 0; j < 4; j++)
#pragma unroll
            for (int e = 0; e < 4; e++) out[i][j][e] = 0.f;

#pragma unroll
    for (int kv = 0; kv < 4; kv++) {
        uint32_t vH[2][4], vL[2][4];
#pragma unroll
        for (int dn = 0; dn < 2; dn++) {
            int r  = kv * 16 + (lane & 7) + (((lane >> 3) & 1) << 3);
            int ch = dn * 2 + (lane >> 4);
            uint32_t off = (uint32_t)(r * 64 + ((ch ^ (r & 3)) << 4));
            LDSM4T(vH[dn][0], vH[dn][1], vH[dn][2], vH[dn][3], vhb + off);
            LDSM4T(vL[dn][0], vL[dn][1], vL[dn][2], vL[dn][3], vlb + off);
        }
#pragma unroll
        for (int i = 0; i < 2; i++) {
            uint32_t pH[4], pL[4];
            pH[0] = pack_hi(sc[i][2 * kv][0], sc[i][2 * kv][1]);
            pH[1] = pack_hi(sc[i][2 * kv][2], sc[i][2 * kv][3]);
            pH[2] = pack_hi(sc[i][2 * kv + 1][0], sc[i][2 * kv + 1][1]);
            pH[3] = pack_hi(sc[i][2 * kv + 1][2], sc[i][2 * kv + 1][3]);
            pL[0] = pack_lo(sc[i][2 * kv][0], sc[i][2 * kv][1]);
            pL[1] = pack_lo(sc[i][2 * kv][2], sc[i][2 * kv][3]);
            pL[2] = pack_lo(sc[i][2 * kv + 1][0], sc[i][2 * kv + 1][1]);
            pL[3] = pack_lo(sc[i][2 * kv + 1][2], sc[i][2 * kv + 1][3]);
#pragma unroll
            for (int dt = 0; dt < 4; dt++) {
                int bi = dt >> 1, bo = (dt & 1) * 2;
                MMA16816(out[i][dt], pH, vH[bi][bo], vH[bi][bo + 1]);
            }
#pragma unroll
            for (int dt = 0; dt < 4; dt++) {
                int bi = dt >> 1, bo = (dt & 1) * 2;
                MMA16816(out[i][dt], pH, vL[bi][bo], vL[bi][bo + 1]);
            }
#pragma unroll
            for (int dt = 0; dt < 4; dt++) {
                int bi = dt >> 1, bo = (dt & 1) * 2;
                MMA16816(out[i][dt], pL, vH[bi][bo], vH[bi][bo + 1]);
            }
        }
    }

#pragma unroll
    for (int i = 0; i < 2; i++) {
        int rA = wq * 32 + i * 16 + gr;
#pragma unroll
        for (int hf = 0; hf < 2; hf++) {
            int r = rA + hf * 8;
            float inv = invs[i][hf];
            size_t base = (size_t)(bw * 64 + r) * 192 + head * 32;
#pragma unroll
            for (int dt = 0; dt < 4; dt++) {
                int c = 8 * dt + 2 * lam;
                float v0 = out[i][dt][hf * 2 + 0] * inv;
                float v1 = out[i][dt][hf * 2 + 1] * inv;
                *(__half2*)(oh + base + c) =
                    __halves2half2(__float2half(v0), __float2half(v1));
            }
        }
    }
}

// ---------------------------------------------------------------------------
// Launch
// ---------------------------------------------------------------------------
extern "C" void kernel_launch(void* const* d_in, const int* in_sizes, int n_in,
                              void* d_out, int out_size)
{
    const float* x    = (const float*)d_in[0];
    const float* n1g  = (const float*)d_in[1];
    const float* n1b  = (const float*)d_in[2];
    const float* qkvw = (const float*)d_in[3];
    const float* qkvb = (const float*)d_in[4];
    const float* tbl  = (const float*)d_in[5];
    const float* pw   = (const float*)d_in[6];
    const float* pb   = (const float*)d_in[7];
    const float* n2g  = (const float*)d_in[8];
    const float* n2b  = (const float*)d_in[9];
    const float* f1w  = (const float*)d_in[10];
    const float* f1b  = (const float*)d_in[11];
    const float* f2w  = (const float*)d_in[12];
    const float* f2b  = (const float*)d_in[13];
    float* xo = (float*)d_out;

    __half *ah, *bh, *bl, *wh;
    cudaGetSymbolAddress((void**)&ah, g_ah);
    cudaGetSymbolAddress((void**)&bh, g_bh);
    cudaGetSymbolAddress((void**)&bl, g_bl);
    cudaGetSymbolAddress((void**)&wh, g_wh);

    cudaFuncSetAttribute(gemm_mma<MODE_QKV>,    cudaFuncAttributeMaxDynamicSharedMemorySize, GEMM_SMEM);
    cudaFuncSetAttribute(gemm_mma<MODE_GELU_H>, cudaFuncAttributeMaxDynamicSharedMemorySize, GEMM_SMEM);
    cudaFuncSetAttribute(gemm_mma<MODE_RESADD>, cudaFuncAttributeMaxDynamicSharedMemorySize, GEMM_SMEM);
    cudaFuncSetAttribute(gemm_mma<MODE_PROJ>,   cudaFuncAttributeMaxDynamicSharedMemorySize, GEMM_SMEM);
    cudaFuncSetAttribute(attn_mma,              cudaFuncAttributeMaxDynamicSharedMemorySize, ATTN_SMEM);

    cvt2_kernel<<<(221184 + 73728 + 255) / 256, 256>>>(
        qkvw, wh + WOFF_QKV, 221184, pw, wh + WOFF_PROJ, 73728);
    cvt2_kernel<<<(294912 + 294912 + 255) / 256, 256>>>(
        f1w, wh + WOFF_FC1, 294912, f2w, wh + WOFF_FC2, 294912);

    for (int dep = 0; dep < 2; dep++) {
        int shift = dep ? 4 : 0;
        const float* resid = dep ? (const float*)xo : x;
        const float* lnsrc = dep ? (const float*)xo : x;
        const __half* wqh = wh + WOFF_QKV  + (size_t)dep * 110592;
        const __half* wph = wh + WOFF_PROJ + (size_t)dep * 36864;
        const __half* w1h = wh + WOFF_FC1  + (size_t)dep * 147456;
        const __half* w2h = wh + WOFF_FC2  + (size_t)dep * 147456;

        // LN1 + shift + window partition -> ah (hi only)
        ln_kernel<<<MROWS / 8, 256>>>(lnsrc, n1g + dep * CC, n1b + dep * CC, ah, shift, 1);

        // QKV GEMM -> (bh, bl): hi+lo for attention, q pre-scaled
        gemm_mma<MODE_QKV><<<dim3(QKVDIM / 64, MROWS / 128), 256, GEMM_SMEM>>>(
            ah, wqh, qkvb + dep * QKVDIM, nullptr, bh, bl, nullptr,
            QKVDIM, CC, 0);

        // Attention (full hi/lo precision) -> ah (hi only)
        attn_mma<<<dim3(NHEAD / 2, BATCH * NWIN), 128, ATTN_SMEM>>>(
            bh, bl, tbl + dep * 225 * NHEAD, ah, shift);

        // Proj GEMM + window reverse + residual(x or xo) -> xo
        gemm_mma<MODE_PROJ><<<dim3(CC / 64, MROWS / 128), 256, GEMM_SMEM>>>(
            ah, wph, pb + dep * CC, xo, nullptr, nullptr, resid,
            CC, CC, shift);

        // LN2 -> ah
        ln_kernel<<<MROWS / 8, 256>>>(xo, n2g + dep * CC, n2b + dep * CC, ah, 0, 0);

        // FC1 GEMM + GELU -> bh (hi only)
        gemm_mma<MODE_GELU_H><<<dim3(MLPDIM / 64, MROWS / 128), 256, GEMM_SMEM>>>(
            ah, w1h, f1b + dep * MLPDIM, nullptr, bh, nullptr, nullptr,
            MLPDIM, CC, 0);

        // FC2 GEMM + residual -> xo
        gemm_mma<MODE_RESADD><<<dim3(CC / 64, MROWS / 128), 256, GEMM_SMEM>>>(
            bh, w2h, f2b + dep * CC, xo, nullptr, nullptr, nullptr,
            CC, MLPDIM, 0);
    }
}

// round 16
// speedup vs baseline: 1.2590x; 1.2590x over previous
#include <cuda_runtime.h>
#include <cuda_fp16.h>
#include <cstdint>
#include <math.h>

// Problem constants
#define BATCH   16
#define CC      192
#define NHEAD   6
#define NTOK    64
#define NWIN    64
#define MROWS   65536
#define QKVDIM  576
#define MLPDIM  768
#define SCALE_Q 0.17677669529663687f

// Weight half-buffer offsets (elements)
#define WOFF_QKV  0
#define WOFF_PROJ 221184
#define WOFF_FC1  294912
#define WOFF_FC2  589824
#define WTOTAL    884736

// Scratch (device globals)
__device__ __half g_ah[(size_t)MROWS * 192];   // activations hi (GEMM A inputs)
__device__ __half g_bh[(size_t)MROWS * 768];   // qkv / gelu hi
__device__ __half g_bl[(size_t)MROWS * 768];   // qkv lo (attention only)
__device__ __half g_wh[WTOTAL];                // weights hi only

// ---------------------------------------------------------------------------
// PTX helpers
// ---------------------------------------------------------------------------
__device__ __forceinline__ uint32_t smem_u32(const void* p) {
    uint32_t a;
    asm("{ .reg .u64 t; cvta.to.shared.u64 t, %1; cvt.u32.u64 %0, t; }"
        : "=r"(a) : "l"(p));
    return a;
}

#define CP16(dst, src) \
    asm volatile("cp.async.cg.shared.global [%0], [%1], 16;" :: "r"(dst), "l"(src))

#define LDSM4(r0, r1, r2, r3, addr) \
    asm volatile("ldmatrix.sync.aligned.m8n8.x4.shared.b16 {%0,%1,%2,%3}, [%4];" \
        : "=r"(r0), "=r"(r1), "=r"(r2), "=r"(r3) : "r"(addr))

#define LDSM4T(r0, r1, r2, r3, addr) \
    asm volatile("ldmatrix.sync.aligned.m8n8.x4.trans.shared.b16 {%0,%1,%2,%3}, [%4];" \
        : "=r"(r0), "=r"(r1), "=r"(r2), "=r"(r3) : "r"(addr))

#define MMA16816(d, a, b0, b1) \
    asm volatile("mma.sync.aligned.m16n8k16.row.col.f32.f16.f16.f32 " \
        "{%0,%1,%2,%3},{%4,%5,%6,%7},{%8,%9},{%0,%1,%2,%3};" \
        : "+f"((d)[0]), "+f"((d)[1]), "+f"((d)[2]), "+f"((d)[3]) \
        : "r"((a)[0]), "r"((a)[1]), "r"((a)[2]), "r"((a)[3]), "r"(b0), "r"(b1))

__device__ __forceinline__ uint32_t pack_hi(float x, float y) {
    __half2 h = __halves2half2(__float2half(x), __float2half(y));
    return *(uint32_t*)&h;
}
__device__ __forceinline__ uint32_t pack_lo(float x, float y) {
    __half hx = __float2half(x), hy = __float2half(y);
    __half2 h = __halves2half2(__float2half(x - __half2float(hx)),
                               __float2half(y - __half2float(hy)));
    return *(uint32_t*)&h;
}

// ---------------------------------------------------------------------------
// Weight conversion: two fp32 arrays -> hi fp16 only
// ---------------------------------------------------------------------------
__global__ __launch_bounds__(256) void cvt2_kernel(
    const float* __restrict__ s1, __half* __restrict__ h1, int n1,
    const float* __restrict__ s2, __half* __restrict__ h2, int n2)
{
    int i = blockIdx.x * 256 + threadIdx.x;
    if (i < n1) h1[i] = __float2half(s1[i]);
    else if (i < n1 + n2) h2[i - n1] = __float2half(s2[i - n1]);
}

// ---------------------------------------------------------------------------
// LayerNorm (+ optional shift + window partition) -> fp16 hi only
// ---------------------------------------------------------------------------
__global__ __launch_bounds__(256) void ln_kernel(
    const float* __restrict__ x, const float* __restrict__ gam,
    const float* __restrict__ bet, __half* __restrict__ oh,
    int shift, int windowed)
{
    int warp = threadIdx.x >> 5, lane = threadIdx.x & 31;
    int r = blockIdx.x * 8 + warp;
    int src;
    if (windowed) {
        int bw = r >> 6, tok = r & 63;
        int b_img = bw >> 6, wr = (bw >> 3) & 7, wc = bw & 7;
        int ti = tok >> 3, tj = tok & 7;
        int h = (wr * 8 + ti + shift) & 63;
        int w = (wc * 8 + tj + shift) & 63;
        src = b_img * 4096 + h * 64 + w;
    } else src = r;
    const float* xp = x + (size_t)src * CC;
    float v[6];
    float s = 0.f;
#pragma unroll
    for (int j = 0; j < 6; j++) { v[j] = xp[lane + 32 * j]; s += v[j]; }
#pragma unroll
    for (int o = 16; o; o >>= 1) s += __shfl_xor_sync(0xffffffffu, s, o);
    float mu = s * (1.f / 192.f);
    float q = 0.f;
#pragma unroll
    for (int j = 0; j < 6; j++) { float d = v[j] - mu; q += d * d; }
#pragma unroll
    for (int o = 16; o; o >>= 1) q += __shfl_xor_sync(0xffffffffu, q, o);
    float rstd = rsqrtf(q * (1.f / 192.f) + 1e-5f);
    size_t base = (size_t)r * CC;
#pragma unroll
    for (int j = 0; j < 6; j++) {
        int c = lane + 32 * j;
        float y = (v[j] - mu) * rstd * gam[c] + bet[c];
        oh[base + c] = __float2half(y);
    }
}

// ---------------------------------------------------------------------------
// Pure fp16 tensor GEMM: C = A[M,K] @ W[N,K]^T + bias (1 MMA per k16).
// BM=128, BN=64, BK=64, 256 threads (8 warps, 4x2), warp tile 32x32.
// 3-stage cp.async ring, ONE __syncthreads per k-iteration.
// NO min-blocks reg cap (R15 lesson: spills cost more than occupancy gains).
// ---------------------------------------------------------------------------
#define MODE_QKV     0   // writes hi AND lo (attention consumes both)
#define MODE_GELU_H  1   // writes hi only
#define MODE_RESADD  2
#define MODE_PROJ    3

// stage: Ah 16K @0, Bh 8K @16384
#define STAGE_BYTES 24576
#define GEMM_SMEM   (3 * STAGE_BYTES)   // 73728 -> 2 CTAs/SM

__device__ __forceinline__ int proj_dest(int r, int shift) {
    int bw = r >> 6, tok = r & 63;
    int b_img = bw >> 6, wr = (bw >> 3) & 7, wc = bw & 7;
    int ti = tok >> 3, tj = tok & 7;
    int h = (wr * 8 + ti + shift) & 63;
    int w = (wc * 8 + tj + shift) & 63;
    return b_img * 4096 + h * 64 + w;
}

template<int MODE>
__global__ __launch_bounds__(256) void gemm_mma(
    const __half* __restrict__ Ah,
    const __half* __restrict__ Bh,
    const float* __restrict__ bias, float* __restrict__ Cp,
    __half* __restrict__ Oh, __half* __restrict__ Ol,
    const float* __restrict__ Rsrc,
    int N, int K, int shift)
{
    extern __shared__ char smem[];
    const uint32_t smbase = smem_u32(smem);
    const int tid  = threadIdx.x;
    const int lane = tid & 31, warp = tid >> 5;
    const int wm = warp >> 1, wn = warp & 1;
    const int m0 = blockIdx.y * 128, n0 = blockIdx.x * 64;
    const int lc = tid & 7;
    const int lr = tid >> 3;

    const __half* pAh = Ah + (size_t)m0 * K + lc * 8;
    const __half* pBh = Bh + (size_t)n0 * K + lc * 8;

    const int niter = K >> 6;

    auto issue = [&](int s, int buf) {
        uint32_t sb = smbase + (uint32_t)buf * STAGE_BYTES;
        int k0 = s << 6;
#pragma unroll
        for (int i = 0; i < 4; i++) {
            int r = lr + 32 * i;
            uint32_t d = sb + r * 128 + ((uint32_t)(lc ^ (r & 7)) << 4);
            CP16(d, pAh + (size_t)r * K + k0);
        }
#pragma unroll
        for (int i = 0; i < 2; i++) {
            int r = lr + 32 * i;
            uint32_t d = sb + 16384 + r * 128 + ((uint32_t)(lc ^ (r & 7)) << 4);
            CP16(d, pBh + (size_t)r * K + k0);
        }
        asm volatile("cp.async.commit_group;");
    };

    float acc[2][4][4];
#pragma unroll
    for (int i = 0; i < 2; i++)
#pragma unroll
        for (int j = 0; j < 4; j++)
#pragma unroll
            for (int e = 0; e < 4; e++) acc[i][j][e] = 0.f;

    issue(0, 0);
    if (niter > 1) issue(1, 1);

    int cbuf = 0;   // buffer holding stage s
    int ibuf = 2;   // next buffer to fill (stage s+2)
    for (int s = 0; s < niter; s++) {
        if (s + 1 < niter) asm volatile("cp.async.wait_group 1;");
        else               asm volatile("cp.async.wait_group 0;");
        __syncthreads();
        if (s + 2 < niter) issue(s + 2, ibuf);

        uint32_t sb = smbase + (uint32_t)cbuf * STAGE_BYTES;
#pragma unroll
        for (int kk = 0; kk < 4; kk++) {
            uint32_t aH[2][4], bH[2][4];
#pragma unroll
            for (int i = 0; i < 2; i++) {
                int r  = wm * 32 + i * 16 + (lane & 15);
                int ch = kk * 2 + (lane >> 4);
                uint32_t ad = sb + r * 128 + ((uint32_t)(ch ^ (r & 7)) << 4);
                LDSM4(aH[i][0], aH[i][1], aH[i][2], aH[i][3], ad);
            }
#pragma unroll
            for (int i = 0; i < 2; i++) {
                int grp = lane >> 3;
                int r  = wn * 32 + i * 16 + ((grp >> 1) << 3) + (lane & 7);
                int ch = kk * 2 + (grp & 1);
                uint32_t bd = sb + 16384 + r * 128 + ((uint32_t)(ch ^ (r & 7)) << 4);
                LDSM4(bH[i][0], bH[i][1], bH[i][2], bH[i][3], bd);
            }
#pragma unroll
            for (int i = 0; i < 2; i++)
#pragma unroll
                for (int jj = 0; jj < 4; jj++) {
                    int bi = jj >> 1, bo = (jj & 1) * 2;
                    MMA16816(acc[i][jj], aH[i], bH[bi][bo], bH[bi][bo + 1]);
                }
        }
        cbuf = (cbuf == 2) ? 0 : cbuf + 1;
        ibuf = (ibuf == 2) ? 0 : ibuf + 1;
    }

    // epilogue
#pragma unroll
    for (int i = 0; i < 2; i++) {
        int rb = m0 + wm * 32 + i * 16 + (lane >> 2);
#pragma unroll
        for (int hf = 0; hf < 2; hf++) {
            int r = rb + hf * 8;
            int dest = (MODE == MODE_PROJ) ? proj_dest(r, shift) : r;
#pragma unroll
            for (int jj = 0; jj < 4; jj++) {
                int c = n0 + wn * 32 + jj * 8 + (lane & 3) * 2;
                float v0 = acc[i][jj][hf * 2 + 0] + bias[c];
                float v1 = acc[i][jj][hf * 2 + 1] + bias[c + 1];
                if (MODE == MODE_QKV) {
                    if (c < 192) { v0 *= SCALE_Q; v1 *= SCALE_Q; }
                    __half h0 = __float2half(v0), h1 = __float2half(v1);
                    *(__half2*)(Oh + (size_t)r * N + c) = __halves2half2(h0, h1);
                    *(__half2*)(Ol + (size_t)r * N + c) = __halves2half2(
                        __float2half(v0 - __half2float(h0)),
                        __float2half(v1 - __half2float(h1)));
                } else if (MODE == MODE_GELU_H) {
                    float g0 = 0.5f * v0 * (1.f + erff(v0 * 0.70710678118654752f));
                    float g1 = 0.5f * v1 * (1.f + erff(v1 * 0.70710678118654752f));
                    *(__half2*)(Oh + (size_t)r * N + c) =
                        __halves2half2(__float2half(g0), __float2half(g1));
                } else if (MODE == MODE_RESADD) {
                    float2* p = (float2*)(Cp + (size_t)r * N + c);
                    float2 o = *p; o.x += v0; o.y += v1; *p = o;
                } else { // MODE_PROJ
                    float2 rv = *(const float2*)(Rsrc + (size_t)dest * CC + c);
                    float2 o; o.x = rv.x + v0; o.y = rv.y + v1;
                    *(float2*)(Cp + (size_t)dest * CC + c) = o;
                }
            }
        }
    }
}

// ---------------------------------------------------------------------------
// Tensor-core windowed attention: one CTA = 2 heads (128 threads).
// Full 3-term hi/lo precision for q,k,v; output hi only. (unchanged)
// ---------------------------------------------------------------------------
struct __align__(16) AttnSmem2 {
    __half qh[2][2048], ql[2][2048];
    __half kh[2][2048], kl[2][2048];
    __half vh[2][2048], vl[2][2048];
    float  tbl[2][225];
    unsigned char rel[4096];
    int    rid[64];
};
#define ATTN_SMEM ((int)sizeof(AttnSmem2))

__global__ __launch_bounds__(128) void attn_mma(
    const __half* __restrict__ Qh, const __half* __restrict__ Ql,
    const float* __restrict__ tblg,
    __half* __restrict__ oh, int shift)
{
    extern __shared__ char smraw[];
    AttnSmem2& sm = *reinterpret_cast<AttnSmem2*>(smraw);
    int bw = blockIdx.y;
    int tid = threadIdx.x;
    int sub = tid >> 6, t64 = tid & 63;
    int lane = tid & 31, wq = (t64 >> 5);
    int head = blockIdx.x * 2 + sub;

    __half* bufs[6] = {sm.qh[sub], sm.ql[sub], sm.kh[sub], sm.kl[sub],
                       sm.vh[sub], sm.vl[sub]};
#pragma unroll
    for (int it = 0; it < 24; it++) {
        int idx = t64 + it * 64;
        int buf = idx >> 8, rem = idx & 255, r = rem >> 2, ch = rem & 3;
        int sec = buf >> 1;
        const __half* src = (buf & 1) ? Ql : Qh;
        const __half* p = src + (size_t)(bw * 64 + r) * QKVDIM + sec * 192 + head * 32 + ch * 8;
        uint4 val = *(const uint4*)p;
        *(uint4*)((char*)bufs[buf] + r * 64 + ((ch ^ (r & 3)) << 4)) = val;
    }
    for (int idx = tid; idx < 4096; idx += 128) {
        int n = idx >> 6, m = idx & 63;
        sm.rel[idx] = (unsigned char)(((n >> 3) - (m >> 3) + 7) * 15 + ((n & 7) - (m & 7) + 7));
    }
    for (int idx = t64; idx < 225; idx += 64) sm.tbl[sub][idx] = tblg[idx * NHEAD + head];
    if (tid < 64) {
        int wr = (bw >> 3) & 7, wc = bw & 7;
        int ti = tid >> 3, tj = tid & 7;
        int h = wr * 8 + ti, w = wc * 8 + tj;
        int rh = (h < 56) ? 0 : ((h < 60) ? 1 : 2);
        int rw = (w < 56) ? 0 : ((w < 60) ? 1 : 2);
        sm.rid[tid] = rh * 3 + rw;
    }
    __syncthreads();

    uint32_t qhb = smem_u32(sm.qh[sub]), qlb = smem_u32(sm.ql[sub]);
    uint32_t khb = smem_u32(sm.kh[sub]), klb = smem_u32(sm.kl[sub]);
    uint32_t vhb = smem_u32(sm.vh[sub]), vlb = smem_u32(sm.vl[sub]);

    float sc[2][8][4];
#pragma unroll
    for (int i = 0; i < 2; i++)
#pragma unroll
        for (int j = 0; j < 8; j++)
#pragma unroll
            for (int e = 0; e < 4; e++) sc[i][j][e] = 0.f;

#pragma unroll
    for (int kk = 0; kk < 2; kk++) {
        uint32_t aH[2][4], aL[2][4], bH[4][4], bL[4][4];
#pragma unroll
        for (int i = 0; i < 2; i++) {
            int r  = wq * 32 + i * 16 + (lane & 15);
            int ch = kk * 2 + (lane >> 4);
            uint32_t off = (uint32_t)(r * 64 + ((ch ^ (r & 3)) << 4));
            LDSM4(aH[i][0], aH[i][1], aH[i][2], aH[i][3], qhb + off);
            LDSM4(aL[i][0], aL[i][1], aL[i][2], aL[i][3], qlb + off);
        }
#pragma unroll
        for (int i = 0; i < 4; i++) {
            int grp = lane >> 3;
            int r  = i * 16 + ((grp >> 1) << 3) + (lane & 7);
            int ch = kk * 2 + (grp & 1);
            uint32_t off = (uint32_t)(r * 64 + ((ch ^ (r & 3)) << 4));
            LDSM4(bH[i][0], bH[i][1], bH[i][2], bH[i][3], khb + off);
            LDSM4(bL[i][0], bL[i][1], bL[i][2], bL[i][3], klb + off);
        }
#pragma unroll
        for (int i = 0; i < 2; i++)
#pragma unroll
            for (int j = 0; j < 8; j++) {
                int bi = j >> 1, bo = (j & 1) * 2;
                MMA16816(sc[i][j], aH[i], bH[bi][bo], bH[bi][bo + 1]);
            }
#pragma unroll
        for (int i = 0; i < 2; i++)
#pragma unroll
            for (int j = 0; j < 8; j++) {
                int bi = j >> 1, bo = (j & 1) * 2;
                MMA16816(sc[i][j], aH[i], bL[bi][bo], bL[bi][bo + 1]);
            }
#pragma unroll
        for (int i = 0; i < 2; i++)
#pragma unroll
            for (int j = 0; j < 8; j++) {
                int bi = j >> 1, bo = (j & 1) * 2;
                MMA16816(sc[i][j], aL[i], bH[bi][bo], bH[bi][bo + 1]);
            }
    }

    int gr = lane >> 2, lam = lane & 3;
    float invs[2][2];
#pragma unroll
    for (int i = 0; i < 2; i++) {
        int rA = wq * 32 + i * 16 + gr, rB = rA + 8;
        int ridA = sm.rid[rA], ridB = sm.rid[rB];
        float mxA = -1e30f, mxB = -1e30f;
#pragma unroll
        for (int j = 0; j < 8; j++) {
            int c0 = 8 * j + 2 * lam;
            float b00 = sm.tbl[sub][sm.rel[rA * 64 + c0]];
            float b01 = sm.tbl[sub][sm.rel[rA * 64 + c0 + 1]];
            float b10 = sm.tbl[sub][sm.rel[rB * 64 + c0]];
            float b11 = sm.tbl[sub][sm.rel[rB * 64 + c0 + 1]];
            if (shift) {
                int rc0 = sm.rid[c0], rc1 = sm.rid[c0 + 1];
                if (rc0 != ridA) b00 -= 100.f;
                if (rc1 != ridA) b01 -= 100.f;
                if (rc0 != ridB) b10 -= 100.f;
                if (rc1 != ridB) b11 -= 100.f;
            }
            sc[i][j][0] += b00; sc[i][j][1] += b01;
            sc[i][j][2] += b10; sc[i][j][3] += b11;
            mxA = fmaxf(mxA, fmaxf(sc[i][j][0], sc[i][j][1]));
            mxB = fmaxf(mxB, fmaxf(sc[i][j][2], sc[i][j][3]));
        }
        mxA = fmaxf(mxA, __shfl_xor_sync(0xffffffffu, mxA, 1));
        mxA = fmaxf(mxA, __shfl_xor_sync(0xffffffffu, mxA, 2));
        mxB = fmaxf(mxB, __shfl_xor_sync(0xffffffffu, mxB, 1));
        mxB = fmaxf(mxB, __shfl_xor_sync(0xffffffffu, mxB, 2));
        float sA = 0.f, sB = 0.f;
#pragma unroll
        for (int j = 0; j < 8; j++) {
            sc[i][j][0] = __expf(sc[i][j][0] - mxA); sA += sc[i][j][0];
            sc[i][j][1] = __expf(sc[i][j][1] - mxA); sA += sc[i][j][1];
            sc[i][j][2] = __expf(sc[i][j][2] - mxB); sB += sc[i][j][2];
            sc[i][j][3] = __expf(sc[i][j][3] - mxB); sB += sc[i][j][3];
        }
        sA += __shfl_xor_sync(0xffffffffu, sA, 1);
        sA += __shfl_xor_sync(0xffffffffu, sA, 2);
        sB += __shfl_xor_sync(0xffffffffu, sB, 1);
        sB += __shfl_xor_sync(0xffffffffu, sB, 2);
        invs[i][0] = 1.f / sA;
        invs[i][1] = 1.f / sB;
    }

    float out[2][4][4];
#pragma unroll
    for (int i = 0; i < 2; i++)
#pragma unroll
        for (int j = 0; j < 4; j++)
#pragma unroll
            for (int e = 0; e < 4; e++) out[i][j][e] = 0.f;

#pragma unroll
    for (int kv = 0; kv < 4; kv++) {
        uint32_t vH[2][4], vL[2][4];
#pragma unroll
        for (int dn = 0; dn < 2; dn++) {
            int r  = kv * 16 + (lane & 7) + (((lane >> 3) & 1) << 3);
            int ch = dn * 2 + (lane >> 4);
            uint32_t off = (uint32_t)(r * 64 + ((ch ^ (r & 3)) << 4));
            LDSM4T(vH[dn][0], vH[dn][1], vH[dn][2], vH[dn][3], vhb + off);
            LDSM4T(vL[dn][0], vL[dn][1], vL[dn][2], vL[dn][3], vlb + off);
        }
#pragma unroll
        for (int i = 0; i < 2; i++) {
            uint32_t pH[4], pL[4];
            pH[0] = pack_hi(sc[i][2 * kv][0], sc[i][2 * kv][1]);
            pH[1] = pack_hi(sc[i][2 * kv][2], sc[i][2 * kv][3]);
            pH[2] = pack_hi(sc[i][2 * kv + 1][0], sc[i][2 * kv + 1][1]);
            pH[3] = pack_hi(sc[i][2 * kv + 1][2], sc[i][2 * kv + 1][3]);
            pL[0] = pack_lo(sc[i][2 * kv][0], sc[i][2 * kv][1]);
            pL[1] = pack_lo(sc[i][2 * kv][2], sc[i][2 * kv][3]);
            pL[2] = pack_lo(sc[i][2 * kv + 1][0], sc[i][2 * kv + 1][1]);
            pL[3] = pack_lo(sc[i][2 * kv + 1][2], sc[i][2 * kv + 1][3]);
#pragma unroll
            for (int dt = 0; dt < 4; dt++) {
                int bi = dt >> 1, bo = (dt & 1) * 2;
                MMA16816(out[i][dt], pH, vH[bi][bo], vH[bi][bo + 1]);
            }
#pragma unroll
            for (int dt = 0; dt < 4; dt++) {
                int bi = dt >> 1, bo = (dt & 1) * 2;
                MMA16816(out[i][dt], pH, vL[bi][bo], vL[bi][bo + 1]);
            }
#pragma unroll
            for (int dt = 0; dt < 4; dt++) {
                int bi = dt >> 1, bo = (dt & 1) * 2;
                MMA16816(out[i][dt], pL, vH[bi][bo], vH[bi][bo + 1]);
            }
        }
    }

#pragma unroll
    for (int i = 0; i < 2; i++) {
        int rA = wq * 32 + i * 16 + gr;
#pragma unroll
        for (int hf = 0; hf < 2; hf++) {
            int r = rA + hf * 8;
            float inv = invs[i][hf];
            size_t base = (size_t)(bw * 64 + r) * 192 + head * 32;
#pragma unroll
            for (int dt = 0; dt < 4; dt++) {
                int c = 8 * dt + 2 * lam;
                float v0 = out[i][dt][hf * 2 + 0] * inv;
                float v1 = out[i][dt][hf * 2 + 1] * inv;
                *(__half2*)(oh + base + c) =
                    __halves2half2(__float2half(v0), __float2half(v1));
            }
        }
    }
}

// ---------------------------------------------------------------------------
// Launch
// ---------------------------------------------------------------------------
extern "C" void kernel_launch(void* const* d_in, const int* in_sizes, int n_in,
                              void* d_out, int out_size)
{
    const float* x    = (const float*)d_in[0];
    const float* n1g  = (const float*)d_in[1];
    const float* n1b  = (const float*)d_in[2];
    const float* qkvw = (const float*)d_in[3];
    const float* qkvb = (const float*)d_in[4];
    const float* tbl  = (const float*)d_in[5];
    const float* pw   = (const float*)d_in[6];
    const float* pb   = (const float*)d_in[7];
    const float* n2g  = (const float*)d_in[8];
    const float* n2b  = (const float*)d_in[9];
    const float* f1w  = (const float*)d_in[10];
    const float* f1b  = (const float*)d_in[11];
    const float* f2w  = (const float*)d_in[12];
    const float* f2b  = (const float*)d_in[13];
    float* xo = (float*)d_out;

    __half *ah, *bh, *bl, *wh;
    cudaGetSymbolAddress((void**)&ah, g_ah);
    cudaGetSymbolAddress((void**)&bh, g_bh);
    cudaGetSymbolAddress((void**)&bl, g_bl);
    cudaGetSymbolAddress((void**)&wh, g_wh);

    cudaFuncSetAttribute(gemm_mma<MODE_QKV>,    cudaFuncAttributeMaxDynamicSharedMemorySize, GEMM_SMEM);
    cudaFuncSetAttribute(gemm_mma<MODE_GELU_H>, cudaFuncAttributeMaxDynamicSharedMemorySize, GEMM_SMEM);
    cudaFuncSetAttribute(gemm_mma<MODE_RESADD>, cudaFuncAttributeMaxDynamicSharedMemorySize, GEMM_SMEM);
    cudaFuncSetAttribute(gemm_mma<MODE_PROJ>,   cudaFuncAttributeMaxDynamicSharedMemorySize, GEMM_SMEM);
    cudaFuncSetAttribute(attn_mma,              cudaFuncAttributeMaxDynamicSharedMemorySize, ATTN_SMEM);

    cvt2_kernel<<<(221184 + 73728 + 255) / 256, 256>>>(
        qkvw, wh + WOFF_QKV, 221184, pw, wh + WOFF_PROJ, 73728);
    cvt2_kernel<<<(294912 + 294912 + 255) / 256, 256>>>(
        f1w, wh + WOFF_FC1, 294912, f2w, wh + WOFF_FC2, 294912);

    for (int dep = 0; dep < 2; dep++) {
        int shift = dep ? 4 : 0;
        const float* resid = dep ? (const float*)xo : x;
        const float* lnsrc = dep ? (const float*)xo : x;
        const __half* wqh = wh + WOFF_QKV  + (size_t)dep * 110592;
        const __half* wph = wh + WOFF_PROJ + (size_t)dep * 36864;
        const __half* w1h = wh + WOFF_FC1  + (size_t)dep * 147456;
        const __half* w2h = wh + WOFF_FC2  + (size_t)dep * 147456;

        // LN1 + shift + window partition -> ah (hi only)
        ln_kernel<<<MROWS / 8, 256>>>(lnsrc, n1g + dep * CC, n1b + dep * CC, ah, shift, 1);

        // QKV GEMM -> (bh, bl): hi+lo for attention, q pre-scaled
        gemm_mma<MODE_QKV><<<dim3(QKVDIM / 64, MROWS / 128), 256, GEMM_SMEM>>>(
            ah, wqh, qkvb + dep * QKVDIM, nullptr, bh, bl, nullptr,
            QKVDIM, CC, 0);

        // Attention (full hi/lo precision) -> ah (hi only)
        attn_mma<<<dim3(NHEAD / 2, BATCH * NWIN), 128, ATTN_SMEM>>>(
            bh, bl, tbl + dep * 225 * NHEAD, ah, shift);

        // Proj GEMM + window reverse + residual(x or xo) -> xo
        gemm_mma<MODE_PROJ><<<dim3(CC / 64, MROWS / 128), 256, GEMM_SMEM>>>(
            ah, wph, pb + dep * CC, xo, nullptr, nullptr, resid,
            CC, CC, shift);

        // LN2 -> ah
        ln_kernel<<<MROWS / 8, 256>>>(xo, n2g + dep * CC, n2b + dep * CC, ah, 0, 0);

        // FC1 GEMM + GELU -> bh (hi only)
        gemm_mma<MODE_GELU_H><<<dim3(MLPDIM / 64, MROWS / 128), 256, GEMM_SMEM>>>(
            ah, w1h, f1b + dep * MLPDIM, nullptr, bh, nullptr, nullptr,
            MLPDIM, CC, 0);

        // FC2 GEMM + residual -> xo
        gemm_mma<MODE_RESADD><<<dim3(CC / 64, MROWS / 128), 256, GEMM_SMEM>>>(
            bh, w2h, f2b + dep * CC, xo, nullptr, nullptr, nullptr,
            CC, MLPDIM, 0);
    }
}

// round 17
// speedup vs baseline: 1.4698x; 1.1674x over previous
#include <cuda_runtime.h>
#include <cuda_fp16.h>
#include <cstdint>
#include <math.h>

// Problem constants
#define BATCH   16
#define CC      192
#define NHEAD   6
#define NTOK    64
#define NWIN    64
#define MROWS   65536
#define QKVDIM  576
#define MLPDIM  768
#define SCALE_Q 0.17677669529663687f

// Weight half-buffer offsets (elements)
#define WOFF_QKV  0
#define WOFF_PROJ 221184
#define WOFF_FC1  294912
#define WOFF_FC2  589824
#define WTOTAL    884736

// Scratch (device globals)
__device__ __half g_ah[(size_t)MROWS * 192];   // activations hi (GEMM A inputs)
__device__ __half g_bh[(size_t)MROWS * 768];   // qkv / gelu hi
__device__ __half g_wh[WTOTAL];                // weights hi only

// ---------------------------------------------------------------------------
// PTX helpers
// ---------------------------------------------------------------------------
__device__ __forceinline__ uint32_t smem_u32(const void* p) {
    uint32_t a;
    asm("{ .reg .u64 t; cvta.to.shared.u64 t, %1; cvt.u32.u64 %0, t; }"
        : "=r"(a) : "l"(p));
    return a;
}

#define CP16(dst, src) \
    asm volatile("cp.async.cg.shared.global [%0], [%1], 16;" :: "r"(dst), "l"(src))

#define LDSM4(r0, r1, r2, r3, addr) \
    asm volatile("ldmatrix.sync.aligned.m8n8.x4.shared.b16 {%0,%1,%2,%3}, [%4];" \
        : "=r"(r0), "=r"(r1), "=r"(r2), "=r"(r3) : "r"(addr))

#define LDSM4T(r0, r1, r2, r3, addr) \
    asm volatile("ldmatrix.sync.aligned.m8n8.x4.trans.shared.b16 {%0,%1,%2,%3}, [%4];" \
        : "=r"(r0), "=r"(r1), "=r"(r2), "=r"(r3) : "r"(addr))

#define MMA16816(d, a, b0, b1) \
    asm volatile("mma.sync.aligned.m16n8k16.row.col.f32.f16.f16.f32 " \
        "{%0,%1,%2,%3},{%4,%5,%6,%7},{%8,%9},{%0,%1,%2,%3};" \
        : "+f"((d)[0]), "+f"((d)[1]), "+f"((d)[2]), "+f"((d)[3]) \
        : "r"((a)[0]), "r"((a)[1]), "r"((a)[2]), "r"((a)[3]), "r"(b0), "r"(b1))

__device__ __forceinline__ uint32_t pack_hi(float x, float y) {
    __half2 h = __halves2half2(__float2half(x), __float2half(y));
    return *(uint32_t*)&h;
}

// ---------------------------------------------------------------------------
// Weight conversion: two fp32 arrays -> hi fp16 only
// ---------------------------------------------------------------------------
__global__ __launch_bounds__(256) void cvt2_kernel(
    const float* __restrict__ s1, __half* __restrict__ h1, int n1,
    const float* __restrict__ s2, __half* __restrict__ h2, int n2)
{
    int i = blockIdx.x * 256 + threadIdx.x;
    if (i < n1) h1[i] = __float2half(s1[i]);
    else if (i < n1 + n2) h2[i - n1] = __float2half(s2[i - n1]);
}

// ---------------------------------------------------------------------------
// LayerNorm (+ optional shift + window partition) -> fp16 hi only
// ---------------------------------------------------------------------------
__global__ __launch_bounds__(256) void ln_kernel(
    const float* __restrict__ x, const float* __restrict__ gam,
    const float* __restrict__ bet, __half* __restrict__ oh,
    int shift, int windowed)
{
    int warp = threadIdx.x >> 5, lane = threadIdx.x & 31;
    int r = blockIdx.x * 8 + warp;
    int src;
    if (windowed) {
        int bw = r >> 6, tok = r & 63;
        int b_img = bw >> 6, wr = (bw >> 3) & 7, wc = bw & 7;
        int ti = tok >> 3, tj = tok & 7;
        int h = (wr * 8 + ti + shift) & 63;
        int w = (wc * 8 + tj + shift) & 63;
        src = b_img * 4096 + h * 64 + w;
    } else src = r;
    const float* xp = x + (size_t)src * CC;
    float v[6];
    float s = 0.f;
#pragma unroll
    for (int j = 0; j < 6; j++) { v[j] = xp[lane + 32 * j]; s += v[j]; }
#pragma unroll
    for (int o = 16; o; o >>= 1) s += __shfl_xor_sync(0xffffffffu, s, o);
    float mu = s * (1.f / 192.f);
    float q = 0.f;
#pragma unroll
    for (int j = 0; j < 6; j++) { float d = v[j] - mu; q += d * d; }
#pragma unroll
    for (int o = 16; o; o >>= 1) q += __shfl_xor_sync(0xffffffffu, q, o);
    float rstd = rsqrtf(q * (1.f / 192.f) + 1e-5f);
    size_t base = (size_t)r * CC;
#pragma unroll
    for (int j = 0; j < 6; j++) {
        int c = lane + 32 * j;
        float y = (v[j] - mu) * rstd * gam[c] + bet[c];
        oh[base + c] = __float2half(y);
    }
}

// ---------------------------------------------------------------------------
// Pure fp16 tensor GEMM: C = A[M,K] @ W[N,K]^T + bias (1 MMA per k16).
// BM=128, BN=64, BK=64, 256 threads (8 warps, 4x2), warp tile 32x32.
// 3-stage cp.async ring, ONE __syncthreads per k-iteration. (R16 champion)
// ---------------------------------------------------------------------------
#define MODE_QKV     0   // writes hi only
#define MODE_GELU_H  1
#define MODE_RESADD  2
#define MODE_PROJ    3

// stage: Ah 16K @0, Bh 8K @16384
#define STAGE_BYTES 24576
#define GEMM_SMEM   (3 * STAGE_BYTES)   // 73728 -> 3 CTAs/SM

__device__ __forceinline__ int proj_dest(int r, int shift) {
    int bw = r >> 6, tok = r & 63;
    int b_img = bw >> 6, wr = (bw >> 3) & 7, wc = bw & 7;
    int ti = tok >> 3, tj = tok & 7;
    int h = (wr * 8 + ti + shift) & 63;
    int w = (wc * 8 + tj + shift) & 63;
    return b_img * 4096 + h * 64 + w;
}

template<int MODE>
__global__ __launch_bounds__(256) void gemm_mma(
    const __half* __restrict__ Ah,
    const __half* __restrict__ Bh,
    const float* __restrict__ bias, float* __restrict__ Cp,
    __half* __restrict__ Oh,
    const float* __restrict__ Rsrc,
    int N, int K, int shift)
{
    extern __shared__ char smem[];
    const uint32_t smbase = smem_u32(smem);
    const int tid  = threadIdx.x;
    const int lane = tid & 31, warp = tid >> 5;
    const int wm = warp >> 1, wn = warp & 1;
    const int m0 = blockIdx.y * 128, n0 = blockIdx.x * 64;
    const int lc = tid & 7;
    const int lr = tid >> 3;

    const __half* pAh = Ah + (size_t)m0 * K + lc * 8;
    const __half* pBh = Bh + (size_t)n0 * K + lc * 8;

    const int niter = K >> 6;

    auto issue = [&](int s, int buf) {
        uint32_t sb = smbase + (uint32_t)buf * STAGE_BYTES;
        int k0 = s << 6;
#pragma unroll
        for (int i = 0; i < 4; i++) {
            int r = lr + 32 * i;
            uint32_t d = sb + r * 128 + ((uint32_t)(lc ^ (r & 7)) << 4);
            CP16(d, pAh + (size_t)r * K + k0);
        }
#pragma unroll
        for (int i = 0; i < 2; i++) {
            int r = lr + 32 * i;
            uint32_t d = sb + 16384 + r * 128 + ((uint32_t)(lc ^ (r & 7)) << 4);
            CP16(d, pBh + (size_t)r * K + k0);
        }
        asm volatile("cp.async.commit_group;");
    };

    float acc[2][4][4];
#pragma unroll
    for (int i = 0; i < 2; i++)
#pragma unroll
        for (int j = 0; j < 4; j++)
#pragma unroll
            for (int e = 0; e < 4; e++) acc[i][j][e] = 0.f;

    issue(0, 0);
    if (niter > 1) issue(1, 1);

    int cbuf = 0;
    int ibuf = 2;
    for (int s = 0; s < niter; s++) {
        if (s + 1 < niter) asm volatile("cp.async.wait_group 1;");
        else               asm volatile("cp.async.wait_group 0;");
        __syncthreads();
        if (s + 2 < niter) issue(s + 2, ibuf);

        uint32_t sb = smbase + (uint32_t)cbuf * STAGE_BYTES;
#pragma unroll
        for (int kk = 0; kk < 4; kk++) {
            uint32_t aH[2][4], bH[2][4];
#pragma unroll
            for (int i = 0; i < 2; i++) {
                int r  = wm * 32 + i * 16 + (lane & 15);
                int ch = kk * 2 + (lane >> 4);
                uint32_t ad = sb + r * 128 + ((uint32_t)(ch ^ (r & 7)) << 4);
                LDSM4(aH[i][0], aH[i][1], aH[i][2], aH[i][3], ad);
            }
#pragma unroll
            for (int i = 0; i < 2; i++) {
                int grp = lane >> 3;
                int r  = wn * 32 + i * 16 + ((grp >> 1) << 3) + (lane & 7);
                int ch = kk * 2 + (grp & 1);
                uint32_t bd = sb + 16384 + r * 128 + ((uint32_t)(ch ^ (r & 7)) << 4);
                LDSM4(bH[i][0], bH[i][1], bH[i][2], bH[i][3], bd);
            }
#pragma unroll
            for (int i = 0; i < 2; i++)
#pragma unroll
                for (int jj = 0; jj < 4; jj++) {
                    int bi = jj >> 1, bo = (jj & 1) * 2;
                    MMA16816(acc[i][jj], aH[i], bH[bi][bo], bH[bi][bo + 1]);
                }
        }
        cbuf = (cbuf == 2) ? 0 : cbuf + 1;
        ibuf = (ibuf == 2) ? 0 : ibuf + 1;
    }

    // epilogue
#pragma unroll
    for (int i = 0; i < 2; i++) {
        int rb = m0 + wm * 32 + i * 16 + (lane >> 2);
#pragma unroll
        for (int hf = 0; hf < 2; hf++) {
            int r = rb + hf * 8;
            int dest = (MODE == MODE_PROJ) ? proj_dest(r, shift) : r;
#pragma unroll
            for (int jj = 0; jj < 4; jj++) {
                int c = n0 + wn * 32 + jj * 8 + (lane & 3) * 2;
                float v0 = acc[i][jj][hf * 2 + 0] + bias[c];
                float v1 = acc[i][jj][hf * 2 + 1] + bias[c + 1];
                if (MODE == MODE_QKV) {
                    if (c < 192) { v0 *= SCALE_Q; v1 *= SCALE_Q; }
                    *(__half2*)(Oh + (size_t)r * N + c) =
                        __halves2half2(__float2half(v0), __float2half(v1));
                } else if (MODE == MODE_GELU_H) {
                    float g0 = 0.5f * v0 * (1.f + erff(v0 * 0.70710678118654752f));
                    float g1 = 0.5f * v1 * (1.f + erff(v1 * 0.70710678118654752f));
                    *(__half2*)(Oh + (size_t)r * N + c) =
                        __halves2half2(__float2half(g0), __float2half(g1));
                } else if (MODE == MODE_RESADD) {
                    float2* p = (float2*)(Cp + (size_t)r * N + c);
                    float2 o = *p; o.x += v0; o.y += v1; *p = o;
                } else { // MODE_PROJ
                    float2 rv = *(const float2*)(Rsrc + (size_t)dest * CC + c);
                    float2 o; o.x = rv.x + v0; o.y = rv.y + v1;
                    *(float2*)(Cp + (size_t)dest * CC + c) = o;
                }
            }
        }
    }
}

// ---------------------------------------------------------------------------
// Tensor-core windowed attention, hi-only (1-term QK^T and P.V).
// One CTA = 2 heads (128 threads); smem ~30KB.
// ---------------------------------------------------------------------------
struct __align__(16) AttnSmem2 {
    __half qh[2][2048];
    __half kh[2][2048];
    __half vh[2][2048];
    float  tbl[2][225];
    unsigned char rel[4096];
    int    rid[64];
};
#define ATTN_SMEM ((int)sizeof(AttnSmem2))

__global__ __launch_bounds__(128) void attn_mma(
    const __half* __restrict__ Qh,
    const float* __restrict__ tblg,
    __half* __restrict__ oh, int shift)
{
    extern __shared__ char smraw[];
    AttnSmem2& sm = *reinterpret_cast<AttnSmem2*>(smraw);
    int bw = blockIdx.y;
    int tid = threadIdx.x;
    int sub = tid >> 6, t64 = tid & 63;
    int lane = tid & 31, wq = (t64 >> 5);
    int head = blockIdx.x * 2 + sub;

    __half* bufs[3] = {sm.qh[sub], sm.kh[sub], sm.vh[sub]};
#pragma unroll
    for (int it = 0; it < 12; it++) {
        int idx = t64 + it * 64;
        int buf = idx >> 8, rem = idx & 255, r = rem >> 2, ch = rem & 3;
        const __half* p = Qh + (size_t)(bw * 64 + r) * QKVDIM + buf * 192 + head * 32 + ch * 8;
        uint4 val = *(const uint4*)p;
        *(uint4*)((char*)bufs[buf] + r * 64 + ((ch ^ (r & 3)) << 4)) = val;
    }
    for (int idx = tid; idx < 4096; idx += 128) {
        int n = idx >> 6, m = idx & 63;
        sm.rel[idx] = (unsigned char)(((n >> 3) - (m >> 3) + 7) * 15 + ((n & 7) - (m & 7) + 7));
    }
    for (int idx = t64; idx < 225; idx += 64) sm.tbl[sub][idx] = tblg[idx * NHEAD + head];
    if (tid < 64) {
        int wr = (bw >> 3) & 7, wc = bw & 7;
        int ti = tid >> 3, tj = tid & 7;
        int h = wr * 8 + ti, w = wc * 8 + tj;
        int rh = (h < 56) ? 0 : ((h < 60) ? 1 : 2);
        int rw = (w < 56) ? 0 : ((w < 60) ? 1 : 2);
        sm.rid[tid] = rh * 3 + rw;
    }
    __syncthreads();

    uint32_t qhb = smem_u32(sm.qh[sub]);
    uint32_t khb = smem_u32(sm.kh[sub]);
    uint32_t vhb = smem_u32(sm.vh[sub]);

    // ---- QK^T (hi only) ----
    float sc[2][8][4];
#pragma unroll
    for (int i = 0; i < 2; i++)
#pragma unroll
        for (int j = 0; j < 8; j++)
#pragma unroll
            for (int e = 0; e < 4; e++) sc[i][j][e] = 0.f;

#pragma unroll
    for (int kk = 0; kk < 2; kk++) {
        uint32_t aH[2][4], bH[4][4];
#pragma unroll
        for (int i = 0; i < 2; i++) {
            int r  = wq * 32 + i * 16 + (lane & 15);
            int ch = kk * 2 + (lane >> 4);
            uint32_t off = (uint32_t)(r * 64 + ((ch ^ (r & 3)) << 4));
            LDSM4(aH[i][0], aH[i][1], aH[i][2], aH[i][3], qhb + off);
        }
#pragma unroll
        for (int i = 0; i < 4; i++) {
            int grp = lane >> 3;
            int r  = i * 16 + ((grp >> 1) << 3) + (lane & 7);
            int ch = kk * 2 + (grp & 1);
            uint32_t off = (uint32_t)(r * 64 + ((ch ^ (r & 3)) << 4));
            LDSM4(bH[i][0], bH[i][1], bH[i][2], bH[i][3], khb + off);
        }
#pragma unroll
        for (int i = 0; i < 2; i++)
#pragma unroll
            for (int j = 0; j < 8; j++) {
                int bi = j >> 1, bo = (j & 1) * 2;
                MMA16816(sc[i][j], aH[i], bH[bi][bo], bH[bi][bo + 1]);
            }
    }

    // ---- bias + mask + softmax ----
    int gr = lane >> 2, lam = lane & 3;
    float invs[2][2];
#pragma unroll
    for (int i = 0; i < 2; i++) {
        int rA = wq * 32 + i * 16 + gr, rB = rA + 8;
        int ridA = sm.rid[rA], ridB = sm.rid[rB];
        float mxA = -1e30f, mxB = -1e30f;
#pragma unroll
        for (int j = 0; j < 8; j++) {
            int c0 = 8 * j + 2 * lam;
            float b00 = sm.tbl[sub][sm.rel[rA * 64 + c0]];
            float b01 = sm.tbl[sub][sm.rel[rA * 64 + c0 + 1]];
            float b10 = sm.tbl[sub][sm.rel[rB * 64 + c0]];
            float b11 = sm.tbl[sub][sm.rel[rB * 64 + c0 + 1]];
            if (shift) {
                int rc0 = sm.rid[c0], rc1 = sm.rid[c0 + 1];
                if (rc0 != ridA) b00 -= 100.f;
                if (rc1 != ridA) b01 -= 100.f;
                if (rc0 != ridB) b10 -= 100.f;
                if (rc1 != ridB) b11 -= 100.f;
            }
            sc[i][j][0] += b00; sc[i][j][1] += b01;
            sc[i][j][2] += b10; sc[i][j][3] += b11;
            mxA = fmaxf(mxA, fmaxf(sc[i][j][0], sc[i][j][1]));
            mxB = fmaxf(mxB, fmaxf(sc[i][j][2], sc[i][j][3]));
        }
        mxA = fmaxf(mxA, __shfl_xor_sync(0xffffffffu, mxA, 1));
        mxA = fmaxf(mxA, __shfl_xor_sync(0xffffffffu, mxA, 2));
        mxB = fmaxf(mxB, __shfl_xor_sync(0xffffffffu, mxB, 1));
        mxB = fmaxf(mxB, __shfl_xor_sync(0xffffffffu, mxB, 2));
        float sA = 0.f, sB = 0.f;
#pragma unroll
        for (int j = 0; j < 8; j++) {
            sc[i][j][0] = __expf(sc[i][j][0] - mxA); sA += sc[i][j][0];
            sc[i][j][1] = __expf(sc[i][j][1] - mxA); sA += sc[i][j][1];
            sc[i][j][2] = __expf(sc[i][j][2] - mxB); sB += sc[i][j][2];
            sc[i][j][3] = __expf(sc[i][j][3] - mxB); sB += sc[i][j][3];
        }
        sA += __shfl_xor_sync(0xffffffffu, sA, 1);
        sA += __shfl_xor_sync(0xffffffffu, sA, 2);
        sB += __shfl_xor_sync(0xffffffffu, sB, 1);
        sB += __shfl_xor_sync(0xffffffffu, sB, 2);
        invs[i][0] = 1.f / sA;
        invs[i][1] = 1.f / sB;
    }

    // ---- P.V (hi only) ----
    float out[2][4][4];
#pragma unroll
    for (int i = 0; i < 2; i++)
#pragma unroll
        for (int j = 0; j < 4; j++)
#pragma unroll
            for (int e = 0; e < 4; e++) out[i][j][e] = 0.f;

#pragma unroll
    for (int kv = 0; kv < 4; kv++) {
        uint32_t vH[2][4];
#pragma unroll
        for (int dn = 0; dn < 2; dn++) {
            int r  = kv * 16 + (lane & 7) + (((lane >> 3) & 1) << 3);
            int ch = dn * 2 + (lane >> 4);
            uint32_t off = (uint32_t)(r * 64 + ((ch ^ (r & 3)) << 4));
            LDSM4T(vH[dn][0], vH[dn][1], vH[dn][2], vH[dn][3], vhb + off);
        }
#pragma unroll
        for (int i = 0; i < 2; i++) {
            uint32_t pH[4];
            pH[0] = pack_hi(sc[i][2 * kv][0], sc[i][2 * kv][1]);
            pH[1] = pack_hi(sc[i][2 * kv][2], sc[i][2 * kv][3]);
            pH[2] = pack_hi(sc[i][2 * kv + 1][0], sc[i][2 * kv + 1][1]);
            pH[3] = pack_hi(sc[i][2 * kv + 1][2], sc[i][2 * kv + 1][3]);
#pragma unroll
            for (int dt = 0; dt < 4; dt++) {
                int bi = dt >> 1, bo = (dt & 1) * 2;
                MMA16816(out[i][dt], pH, vH[bi][bo], vH[bi][bo + 1]);
            }
        }
    }

    // ---- epilogue ----
#pragma unroll
    for (int i = 0; i < 2; i++) {
        int rA = wq * 32 + i * 16 + gr;
#pragma unroll
        for (int hf = 0; hf < 2; hf++) {
            int r = rA + hf * 8;
            float inv = invs[i][hf];
            size_t base = (size_t)(bw * 64 + r) * 192 + head * 32;
#pragma unroll
            for (int dt = 0; dt < 4; dt++) {
                int c = 8 * dt + 2 * lam;
                float v0 = out[i][dt][hf * 2 + 0] * inv;
                float v1 = out[i][dt][hf * 2 + 1] * inv;
                *(__half2*)(oh + base + c) =
                    __halves2half2(__float2half(v0), __float2half(v1));
            }
        }
    }
}

// ---------------------------------------------------------------------------
// Launch
// ---------------------------------------------------------------------------
extern "C" void kernel_launch(void* const* d_in, const int* in_sizes, int n_in,
                              void* d_out, int out_size)
{
    const float* x    = (const float*)d_in[0];
    const float* n1g  = (const float*)d_in[1];
    const float* n1b  = (const float*)d_in[2];
    const float* qkvw = (const float*)d_in[3];
    const float* qkvb = (const float*)d_in[4];
    const float* tbl  = (const float*)d_in[5];
    const float* pw   = (const float*)d_in[6];
    const float* pb   = (const float*)d_in[7];
    const float* n2g  = (const float*)d_in[8];
    const float* n2b  = (const float*)d_in[9];
    const float* f1w  = (const float*)d_in[10];
    const float* f1b  = (const float*)d_in[11];
    const float* f2w  = (const float*)d_in[12];
    const float* f2b  = (const float*)d_in[13];
    float* xo = (float*)d_out;

    __half *ah, *bh, *wh;
    cudaGetSymbolAddress((void**)&ah, g_ah);
    cudaGetSymbolAddress((void**)&bh, g_bh);
    cudaGetSymbolAddress((void**)&wh, g_wh);

    cudaFuncSetAttribute(gemm_mma<MODE_QKV>,    cudaFuncAttributeMaxDynamicSharedMemorySize, GEMM_SMEM);
    cudaFuncSetAttribute(gemm_mma<MODE_GELU_H>, cudaFuncAttributeMaxDynamicSharedMemorySize, GEMM_SMEM);
    cudaFuncSetAttribute(gemm_mma<MODE_RESADD>, cudaFuncAttributeMaxDynamicSharedMemorySize, GEMM_SMEM);
    cudaFuncSetAttribute(gemm_mma<MODE_PROJ>,   cudaFuncAttributeMaxDynamicSharedMemorySize, GEMM_SMEM);
    cudaFuncSetAttribute(attn_mma,              cudaFuncAttributeMaxDynamicSharedMemorySize, ATTN_SMEM);

    cvt2_kernel<<<(221184 + 73728 + 255) / 256, 256>>>(
        qkvw, wh + WOFF_QKV, 221184, pw, wh + WOFF_PROJ, 73728);
    cvt2_kernel<<<(294912 + 294912 + 255) / 256, 256>>>(
        f1w, wh + WOFF_FC1, 294912, f2w, wh + WOFF_FC2, 294912);

    for (int dep = 0; dep < 2; dep++) {
        int shift = dep ? 4 : 0;
        const float* resid = dep ? (const float*)xo : x;
        const float* lnsrc = dep ? (const float*)xo : x;
        const __half* wqh = wh + WOFF_QKV  + (size_t)dep * 110592;
        const __half* wph = wh + WOFF_PROJ + (size_t)dep * 36864;
        const __half* w1h = wh + WOFF_FC1  + (size_t)dep * 147456;
        const __half* w2h = wh + WOFF_FC2  + (size_t)dep * 147456;

        // LN1 + shift + window partition -> ah (hi only)
        ln_kernel<<<MROWS / 8, 256>>>(lnsrc, n1g + dep * CC, n1b + dep * CC, ah, shift, 1);

        // QKV GEMM -> bh (hi only, q pre-scaled)
        gemm_mma<MODE_QKV><<<dim3(QKVDIM / 64, MROWS / 128), 256, GEMM_SMEM>>>(
            ah, wqh, qkvb + dep * QKVDIM, nullptr, bh, nullptr,
            QKVDIM, CC, 0);

        // Attention (hi only) -> ah
        attn_mma<<<dim3(NHEAD / 2, BATCH * NWIN), 128, ATTN_SMEM>>>(
            bh, tbl + dep * 225 * NHEAD, ah, shift);

        // Proj GEMM + window reverse + residual(x or xo) -> xo
        gemm_mma<MODE_PROJ><<<dim3(CC / 64, MROWS / 128), 256, GEMM_SMEM>>>(
            ah, wph, pb + dep * CC, xo, nullptr, resid,
            CC, CC, shift);

        // LN2 -> ah
        ln_kernel<<<MROWS / 8, 256>>>(xo, n2g + dep * CC, n2b + dep * CC, ah, 0, 0);

        // FC1 GEMM + GELU -> bh (hi only)
        gemm_mma<MODE_GELU_H><<<dim3(MLPDIM / 64, MROWS / 128), 256, GEMM_SMEM>>>(
            ah, w1h, f1b + dep * MLPDIM, nullptr, bh, nullptr,
            MLPDIM, CC, 0);

        // FC2 GEMM + residual -> xo
        gemm_mma<MODE_RESADD><<<dim3(CC / 64, MROWS / 128), 256, GEMM_SMEM>>>(
            bh, w2h, f2b + dep * CC, xo, nullptr, nullptr,
            CC, MLPDIM, 0);
    }
}